// round 1
// baseline (speedup 1.0000x reference)
#include <cuda_runtime.h>

#define BN 8
#define IC 512
#define OC 512
#define HH 32
#define WW 32

// fan_in scaling constants
#define RC_DENSE 0.04419417382415922f     // 1/sqrt(512)
#define RC_CONV  0.014731391274719739f    // 1/sqrt(9*512)

// scratch (no allocations allowed)
__device__ float g_style[BN * IC];   // style[b,ic] = RC_DENSE * (w @ dense_w) + b + 1
__device__ float g_scale[BN * OC];   // RC_CONV * d[b,oc]
__device__ float g_ss[IC * OC];      // sum_k conv_w[k,ic,oc]^2

// ---------------------------------------------------------------------------
// style[b,i] = RC_DENSE * sum_j w[b,j] * dense_w[j,i] + dense_b[i] + 1
// ---------------------------------------------------------------------------
__global__ void style_kernel(const float* __restrict__ w,
                             const float* __restrict__ dense_w,
                             const float* __restrict__ dense_b) {
    __shared__ float wrow[IC];
    int b = blockIdx.x;
    for (int j = threadIdx.x; j < IC; j += blockDim.x) wrow[j] = w[b * IC + j];
    __syncthreads();
    for (int i = threadIdx.x; i < IC; i += blockDim.x) {
        float acc = 0.f;
        #pragma unroll 8
        for (int j = 0; j < IC; j++) acc = fmaf(wrow[j], dense_w[j * IC + i], acc);
        g_style[b * IC + i] = RC_DENSE * acc + dense_b[i] + 1.0f;
    }
}

// ---------------------------------------------------------------------------
// ss[ic,oc] = sum_k conv_w[k,ic,oc]^2
// ---------------------------------------------------------------------------
__global__ void ss_kernel(const float* __restrict__ conv_w) {
    int idx = blockIdx.x * blockDim.x + threadIdx.x;  // ic*OC + oc
    if (idx >= IC * OC) return;
    float s = 0.f;
    #pragma unroll
    for (int k = 0; k < 9; k++) {
        float v = conv_w[k * IC * OC + idx];
        s = fmaf(v, v, s);
    }
    g_ss[idx] = s;
}

// ---------------------------------------------------------------------------
// scale[b,oc] = RC_CONV * rsqrt(RC_CONV^2 * sum_ic style[b,ic]^2 * ss[ic,oc] + 1e-8)
// ---------------------------------------------------------------------------
__global__ void demod_kernel() {
    __shared__ float s2[IC];
    int b = blockIdx.x;
    for (int i = threadIdx.x; i < IC; i += blockDim.x) {
        float s = g_style[b * IC + i];
        s2[i] = s * s;
    }
    __syncthreads();
    for (int oc = threadIdx.x; oc < OC; oc += blockDim.x) {
        float acc = 0.f;
        #pragma unroll 8
        for (int i = 0; i < IC; i++) acc = fmaf(s2[i], g_ss[i * OC + oc], acc);
        g_scale[b * OC + oc] = RC_CONV * rsqrtf(RC_CONV * RC_CONV * acc + 1e-8f);
    }
}

// ---------------------------------------------------------------------------
// Conv: y[b,oc,h,w] = scale[b,oc] * sum_{ic,kh,kw} conv_w[kh,kw,ic,oc]
//                                   * style[b,ic] * x[b,ic,h+kh-1,w+kw-1]
// Block: 64 oc x (4 rows x 32 cols) for one batch. 256 threads.
//   lane (tx&31) = column, ocg (tx>>5) = group of 8 oc.
// ---------------------------------------------------------------------------
#define ICC   8
#define TOC   64
#define TROWS 4

__global__ __launch_bounds__(256, 2)
void conv_kernel(const float* __restrict__ x,
                 const float* __restrict__ conv_w,
                 float* __restrict__ y) {
    int b   = blockIdx.z;
    int oc0 = blockIdx.y * TOC;
    int y0  = blockIdx.x * TROWS;

    __shared__ float s_style[IC];           // 2 KB
    __shared__ float xs[ICC][6][34];        // 6.4 KB  (rows y0-1..y0+4, cols -1..32)
    __shared__ float ws[9][ICC][TOC];       // 18 KB

    int tx   = threadIdx.x;
    int lane = tx & 31;   // output column
    int ocg  = tx >> 5;   // oc group (8 oc each)

    for (int i = tx; i < IC; i += 256) s_style[i] = g_style[b * IC + i];

    float acc[TROWS][8];
    #pragma unroll
    for (int r = 0; r < TROWS; r++)
        #pragma unroll
        for (int o = 0; o < 8; o++) acc[r][o] = 0.f;

    __syncthreads();

    for (int ic0 = 0; ic0 < IC; ic0 += ICC) {
        // ---- load weight slab: ws[k][ic][oc] ----
        #pragma unroll
        for (int t = tx; t < 9 * ICC * TOC; t += 256) {
            int k   = t / (ICC * TOC);
            int rem = t % (ICC * TOC);
            int ic  = rem / TOC;
            int oc  = rem % TOC;
            ws[k][ic][oc] = conv_w[(k * IC + ic0 + ic) * OC + oc0 + oc];
        }
        // ---- load modulated x halo tile ----
        #pragma unroll
        for (int t = tx; t < ICC * 6 * 34; t += 256) {
            int ic  = t / (6 * 34);
            int rem = t % (6 * 34);
            int row = rem / 34;
            int col = rem % 34;
            int gr = y0 - 1 + row;
            int gc = col - 1;
            float v = 0.f;
            if (gr >= 0 && gr < HH && gc >= 0 && gc < WW)
                v = x[((b * IC + ic0 + ic) * HH + gr) * WW + gc] * s_style[ic0 + ic];
            xs[ic][row][col] = v;
        }
        __syncthreads();

        #pragma unroll
        for (int ic = 0; ic < ICC; ic++) {
            // x neighborhood for this thread's column: rows 0..5, cols lane..lane+2
            float xv[6][3];
            #pragma unroll
            for (int rr = 0; rr < 6; rr++)
                #pragma unroll
                for (int c = 0; c < 3; c++)
                    xv[rr][c] = xs[ic][rr][lane + c];

            #pragma unroll
            for (int kh = 0; kh < 3; kh++)
                #pragma unroll
                for (int kw = 0; kw < 3; kw++) {
                    float wv[8];
                    #pragma unroll
                    for (int o = 0; o < 8; o++)
                        wv[o] = ws[kh * 3 + kw][ic][ocg * 8 + o];
                    #pragma unroll
                    for (int r = 0; r < TROWS; r++) {
                        float xvv = xv[r + kh][kw];
                        #pragma unroll
                        for (int o = 0; o < 8; o++)
                            acc[r][o] = fmaf(xvv, wv[o], acc[r][o]);
                    }
                }
        }
        __syncthreads();
    }

    // ---- epilogue: demodulate and store ----
    #pragma unroll
    for (int o = 0; o < 8; o++) {
        int oc = oc0 + ocg * 8 + o;
        float sc = g_scale[b * OC + oc];
        #pragma unroll
        for (int r = 0; r < TROWS; r++)
            y[((b * OC + oc) * HH + y0 + r) * WW + lane] = acc[r][o] * sc;
    }
}

// ---------------------------------------------------------------------------
extern "C" void kernel_launch(void* const* d_in, const int* in_sizes, int n_in,
                              void* d_out, int out_size) {
    const float* x       = (const float*)d_in[0];
    const float* w       = (const float*)d_in[1];
    const float* conv_w  = (const float*)d_in[2];
    const float* dense_w = (const float*)d_in[3];
    const float* dense_b = (const float*)d_in[4];
    float* y = (float*)d_out;

    style_kernel<<<BN, 256>>>(w, dense_w, dense_b);
    ss_kernel<<<(IC * OC) / 256, 256>>>(conv_w);
    demod_kernel<<<BN, 512>>>();

    dim3 grid(HH / TROWS, OC / TOC, BN);   // 8 x 8 x 8
    conv_kernel<<<grid, 256>>>(x, conv_w, y);
}